// round 8
// baseline (speedup 1.0000x reference)
#include <cuda_runtime.h>
#include <cuda_bf16.h>
#include <cstdint>

// VNAttention: B=2, N=2048, C=256, coor=3, H=8, DH=64, e=192, dim_inner=512
#define BB    2
#define NTOK  2048
#define CC    256
#define COOR  3
#define HEADS 8
#define DHEAD 64
#define EDIM  192
#define DI    512
#define TOKS  (BB*NTOK)          // 4096
#define SLABQ (16*NTOK*DHEAD)    // elements per cc-slab: 2,097,152

typedef unsigned long long u64;

// Q/K/V storage: [cc][bh][n][dd]  (e-dim reordered as cc*64+dd; dot-order invariant)
#define QKV_ELEMS (BB*HEADS*NTOK*EDIM)
__device__ __nv_bfloat16 g_Qhi[QKV_ELEMS];
__device__ __nv_bfloat16 g_Qlo[QKV_ELEMS];
__device__ __nv_bfloat16 g_Khi[QKV_ELEMS];
__device__ __nv_bfloat16 g_Klo[QKV_ELEMS];
__device__ __nv_bfloat16 g_Vhi[QKV_ELEMS];
__device__ __nv_bfloat16 g_Vlo[QKV_ELEMS];

// split x, transposed: [c][tok][i]
#define X_ELEMS (COOR*TOKS*CC)
__device__ __nv_bfloat16 g_Xhi[X_ELEMS];
__device__ __nv_bfloat16 g_Xlo[X_ELEMS];
// split weights: Wq,Wk,Wv ([512][256]) then Wo ([256][512])
#define W_ONE  131072
__device__ __nv_bfloat16 g_Whi[4*W_ONE];
__device__ __nv_bfloat16 g_Wlo[4*W_ONE];
// attention output, split, oproj A layout: [c][tok][i2]
#define OA_ELEMS (COOR*TOKS*DI)
__device__ __nv_bfloat16 g_OAhi[OA_ELEMS];
__device__ __nv_bfloat16 g_OAlo[OA_ELEMS];

// ---------------- helpers ----------------
__device__ __forceinline__ uint32_t smem_to_u32(const void* p) {
    uint32_t a;
    asm("{ .reg .u64 t; cvta.to.shared.u64 t, %1; cvt.u32.u64 %0, t; }" : "=r"(a) : "l"(p));
    return a;
}
__device__ __forceinline__ uint32_t pkbf(float x, float y) {
    uint32_t r;
    asm("cvt.rn.bf16x2.f32 %0, %1, %2;" : "=r"(r) : "f"(y), "f"(x));
    return r;
}
// split two floats into packed bf16x2 hi word + lo word
__device__ __forceinline__ void splitpk(float x, float y, uint32_t& hi, uint32_t& lo) {
    __nv_bfloat16 xh = __float2bfloat16(x), yh = __float2bfloat16(y);
    float xr = x - __bfloat162float(xh);
    float yr = y - __bfloat162float(yh);
    hi = (uint32_t)__bfloat16_as_ushort(xh) | ((uint32_t)__bfloat16_as_ushort(yh) << 16);
    lo = pkbf(xr, yr);
}
__device__ __forceinline__ void splitb(float v, __nv_bfloat16& h, __nv_bfloat16& l) {
    h = __float2bfloat16(v);
    l = __float2bfloat16(v - __bfloat162float(h));
}

#define LDSM4(r, addr) \
    asm volatile("ldmatrix.sync.aligned.m8n8.x4.shared.b16 {%0,%1,%2,%3}, [%4];" \
        : "=r"((r)[0]), "=r"((r)[1]), "=r"((r)[2]), "=r"((r)[3]) : "r"(addr))
#define LDSM4T(r, addr) \
    asm volatile("ldmatrix.sync.aligned.m8n8.x4.trans.shared.b16 {%0,%1,%2,%3}, [%4];" \
        : "=r"((r)[0]), "=r"((r)[1]), "=r"((r)[2]), "=r"((r)[3]) : "r"(addr))
#define MMA16816(d, a, b0, b1) \
    asm volatile("mma.sync.aligned.m16n8k16.row.col.f32.bf16.bf16.f32 " \
        "{%0,%1,%2,%3}, {%4,%5,%6,%7}, {%8,%9}, {%0,%1,%2,%3};" \
        : "+f"((d)[0]), "+f"((d)[1]), "+f"((d)[2]), "+f"((d)[3]) \
        : "r"((a)[0]), "r"((a)[1]), "r"((a)[2]), "r"((a)[3]), "r"(b0), "r"(b1))

__device__ __forceinline__ void cpasync16(uint32_t s, const void* g) {
    asm volatile("cp.async.cg.shared.global [%0], [%1], 16;" :: "r"(s), "l"(g));
}
#define CP_COMMIT() asm volatile("cp.async.commit_group;" ::: "memory")
#define CP_WAIT0()  asm volatile("cp.async.wait_group 0;" ::: "memory")

// ============================================================================
// prep kernels
// ============================================================================
__global__ __launch_bounds__(256) void prep_x_kernel(const float* __restrict__ x)
{
    int idx = blockIdx.x * 256 + threadIdx.x;
    float v = x[idx];
    int tok = idx / 768;
    int rem = idx - tok * 768;
    int i = rem / 3, c = rem - i * 3;
    int a = (c * TOKS + tok) * CC + i;
    __nv_bfloat16 h, l; splitb(v, h, l);
    g_Xhi[a] = h; g_Xlo[a] = l;
}

__global__ __launch_bounds__(256) void prep_w_kernel(
    const float* __restrict__ Wq, const float* __restrict__ Wk,
    const float* __restrict__ Wv, const float* __restrict__ Wo)
{
    int idx = blockIdx.x * 256 + threadIdx.x;
    int m = idx >> 17, j = idx & (W_ONE - 1);
    const float* src = (m == 0) ? Wq : (m == 1) ? Wk : (m == 2) ? Wv : Wo;
    float v = src[j];
    __nv_bfloat16 h, l; splitb(v, h, l);
    g_Whi[idx] = h; g_Wlo[idx] = l;
}

// ============================================================================
// Shared HMMA GEMM tile machinery. 128x128, k-tile 64, pass-grouped MMA.
// ============================================================================
#define GROWB 144
#define GT_AHI 0
#define GT_ALO 18432
#define GT_BHI 36864
#define GT_BLO 55296
#define GBUF   73728
#define GEMM_SMEM (2*GBUF)

__device__ __forceinline__ void gemm_load_tile(
    uint32_t sb, int buf, int tid,
    const __nv_bfloat16* Ah, const __nv_bfloat16* Al,
    const __nv_bfloat16* Bh, const __nv_bfloat16* Bl,
    int K, int k0)
{
    uint32_t base = sb + buf * GBUF;
#pragma unroll
    for (int it = 0; it < 16; it++) {
        int idx = tid + 256 * it;
        int arr = idx >> 10;
        int rem = idx & 1023;
        int row = rem >> 3, ch = rem & 7;
        const __nv_bfloat16* src =
            (arr == 0) ? Ah : (arr == 1) ? Al : (arr == 2) ? Bh : Bl;
        cpasync16(base + arr * 18432 + row * GROWB + ch * 16,
                  src + (size_t)row * K + k0 + ch * 8);
    }
    CP_COMMIT();
}

// pass-grouped: 16 independent MMAs between accumulator reuses
#define GEMM_COMPUTE(cacc, bufbase, wr, wc, lane) do { \
    uint32_t _arow = (uint32_t)((wr) * 32 + ((lane) & 15)); \
    uint32_t _acol = (uint32_t)(((lane) >> 4) * 8) * 2; \
    uint32_t _brow = (uint32_t)((wc) * 64 + ((lane) & 7) + (((lane) >> 4) << 3)); \
    uint32_t _bcol = (uint32_t)(((lane) & 8)) * 2; \
    uint32_t _ah = (bufbase) + GT_AHI + _arow * GROWB + _acol; \
    uint32_t _al = (bufbase) + GT_ALO + _arow * GROWB + _acol; \
    uint32_t _bh = (bufbase) + GT_BHI + _brow * GROWB + _bcol; \
    uint32_t _bl = (bufbase) + GT_BLO + _brow * GROWB + _bcol; \
    _Pragma("unroll") \
    for (int ks = 0; ks < 4; ks++) { \
        uint32_t ahi[2][4], alo[2][4], bh[4][4], bl[4][4]; \
        LDSM4(ahi[0], _ah + ks * 32); \
        LDSM4(ahi[1], _ah + 16 * GROWB + ks * 32); \
        LDSM4(alo[0], _al + ks * 32); \
        LDSM4(alo[1], _al + 16 * GROWB + ks * 32); \
        _Pragma("unroll") \
        for (int ng = 0; ng < 4; ng++) { \
            LDSM4(bh[ng], _bh + ng * (16 * GROWB) + ks * 32); \
            LDSM4(bl[ng], _bl + ng * (16 * GROWB) + ks * 32); \
        } \
        _Pragma("unroll") \
        for (int ng = 0; ng < 4; ng++) \
            _Pragma("unroll") \
            for (int mf = 0; mf < 2; mf++) { \
                MMA16816(cacc[mf][2 * ng],     ahi[mf], bh[ng][0], bh[ng][1]); \
                MMA16816(cacc[mf][2 * ng + 1], ahi[mf], bh[ng][2], bh[ng][3]); \
            } \
        _Pragma("unroll") \
        for (int ng = 0; ng < 4; ng++) \
            _Pragma("unroll") \
            for (int mf = 0; mf < 2; mf++) { \
                MMA16816(cacc[mf][2 * ng],     ahi[mf], bl[ng][0], bl[ng][1]); \
                MMA16816(cacc[mf][2 * ng + 1], ahi[mf], bl[ng][2], bl[ng][3]); \
            } \
        _Pragma("unroll") \
        for (int ng = 0; ng < 4; ng++) \
            _Pragma("unroll") \
            for (int mf = 0; mf < 2; mf++) { \
                MMA16816(cacc[mf][2 * ng],     alo[mf], bh[ng][0], bh[ng][1]); \
                MMA16816(cacc[mf][2 * ng + 1], alo[mf], bh[ng][2], bh[ng][3]); \
            } \
    } \
} while (0)

// ============================================================================
// QKV projection GEMM. grid (32 tokTiles, 4 oTiles, 9); epilogue -> [cc] slabs
// ============================================================================
__global__ __launch_bounds__(256) void qkv_hmma(float dummy)
{
    extern __shared__ char smem[];
    const uint32_t sb = smem_to_u32(smem);
    const int tid = threadIdx.x;
    const int lane = tid & 31;
    const int wid = tid >> 5;
    const int wr = wid & 3, wc = wid >> 2;
    const int tok0 = blockIdx.x * 128;
    const int ot = blockIdx.y * 128;
    const int cc = blockIdx.z % 3;
    const int mz = blockIdx.z / 3;

    const __nv_bfloat16* Ah = g_Xhi + (size_t)cc * TOKS * CC + (size_t)tok0 * CC;
    const __nv_bfloat16* Al = g_Xlo + (size_t)cc * TOKS * CC + (size_t)tok0 * CC;
    const __nv_bfloat16* Bh = g_Whi + (size_t)mz * W_ONE + (size_t)ot * CC;
    const __nv_bfloat16* Bl = g_Wlo + (size_t)mz * W_ONE + (size_t)ot * CC;

    float c[2][8][4];
#pragma unroll
    for (int m = 0; m < 2; m++)
#pragma unroll
        for (int n = 0; n < 8; n++)
#pragma unroll
            for (int e = 0; e < 4; e++) c[m][n][e] = 0.0f;

    gemm_load_tile(sb, 0, tid, Ah, Al, Bh, Bl, CC, 0);
    CP_WAIT0();
    __syncthreads();

#pragma unroll
    for (int kt = 0; kt < 4; kt++) {
        if (kt + 1 < 4)
            gemm_load_tile(sb, (kt + 1) & 1, tid, Ah, Al, Bh, Bl, CC, (kt + 1) * 64);
        uint32_t bufbase = sb + (kt & 1) * GBUF;
        GEMM_COMPUTE(c, bufbase, wr, wc, lane);
        if (kt + 1 < 4) { CP_WAIT0(); }
        __syncthreads();
    }

    __nv_bfloat16* dhi = (mz == 0) ? g_Qhi : (mz == 1) ? g_Khi : g_Vhi;
    __nv_bfloat16* dlo = (mz == 0) ? g_Qlo : (mz == 1) ? g_Klo : g_Vlo;
    const float qs = (mz == 0) ? rsqrtf((float)EDIM) : 1.0f;

    const int rbase = wr * 32 + (lane >> 2);
    const int cbase = wc * 64 + 2 * (lane & 3);
#pragma unroll
    for (int mf = 0; mf < 2; mf++) {
#pragma unroll
        for (int h2 = 0; h2 < 2; h2++) {
            int tok = tok0 + rbase + mf * 16 + h2 * 8;
            int b = tok >> 11, n = tok & 2047;
#pragma unroll
            for (int nf = 0; nf < 8; nf++) {
                int o = ot + cbase + nf * 8;        // even; pair (o, o+1) same head
                int hh = o >> 6, dd = o & 63;
                size_t a = (size_t)(cc * 16 + b * 8 + hh) * (NTOK * 64)
                         + (size_t)n * 64 + dd;
                uint32_t hi, lo;
                splitpk(c[mf][nf][2 * h2] * qs, c[mf][nf][2 * h2 + 1] * qs, hi, lo);
                *(uint32_t*)&dhi[a] = hi;
                *(uint32_t*)&dlo[a] = lo;
            }
        }
    }
}

// ============================================================================
// Output projection GEMM. grid (32 tokTiles, 2 oTiles, 3 cc). K = 512.
// ============================================================================
__global__ __launch_bounds__(256) void oproj_hmma(float* __restrict__ out)
{
    extern __shared__ char smem[];
    const uint32_t sb = smem_to_u32(smem);
    const int tid = threadIdx.x;
    const int lane = tid & 31;
    const int wid = tid >> 5;
    const int wr = wid & 3, wc = wid >> 2;
    const int tok0 = blockIdx.x * 128;
    const int ot = blockIdx.y * 128;
    const int cc = blockIdx.z;

    const __nv_bfloat16* Ah = g_OAhi + (size_t)cc * TOKS * DI + (size_t)tok0 * DI;
    const __nv_bfloat16* Al = g_OAlo + (size_t)cc * TOKS * DI + (size_t)tok0 * DI;
    const __nv_bfloat16* Bh = g_Whi + (size_t)3 * W_ONE + (size_t)ot * DI;
    const __nv_bfloat16* Bl = g_Wlo + (size_t)3 * W_ONE + (size_t)ot * DI;

    float c[2][8][4];
#pragma unroll
    for (int m = 0; m < 2; m++)
#pragma unroll
        for (int n = 0; n < 8; n++)
#pragma unroll
            for (int e = 0; e < 4; e++) c[m][n][e] = 0.0f;

    gemm_load_tile(sb, 0, tid, Ah, Al, Bh, Bl, DI, 0);
    CP_WAIT0();
    __syncthreads();

#pragma unroll
    for (int kt = 0; kt < 8; kt++) {
        if (kt + 1 < 8)
            gemm_load_tile(sb, (kt + 1) & 1, tid, Ah, Al, Bh, Bl, DI, (kt + 1) * 64);
        uint32_t bufbase = sb + (kt & 1) * GBUF;
        GEMM_COMPUTE(c, bufbase, wr, wc, lane);
        if (kt + 1 < 8) { CP_WAIT0(); }
        __syncthreads();
    }

    const int rbase = wr * 32 + (lane >> 2);
    const int cbase = wc * 64 + 2 * (lane & 3);
#pragma unroll
    for (int mf = 0; mf < 2; mf++) {
#pragma unroll
        for (int h2 = 0; h2 < 2; h2++) {
            int tok = tok0 + rbase + mf * 16 + h2 * 8;
#pragma unroll
            for (int nf = 0; nf < 8; nf++) {
#pragma unroll
                for (int e2 = 0; e2 < 2; e2++) {
                    int o2 = ot + cbase + nf * 8 + e2;
                    out[((size_t)tok * CC + o2) * 3 + cc] = c[mf][nf][2 * h2 + e2];
                }
            }
        }
    }
}

// ============================================================================
// HMMA flash attention: pass-grouped S, interchanged+grouped PV.
// grid (16 row-tiles, 16 bh), 256 threads, 204800 B dyn smem.
// smem e' = cc*64+dd layout (linear: e' = ch*8).
// ============================================================================
#define ROWB 400
#define SB_QHI 0
#define SB_QLO (SB_QHI + 128 * ROWB)
#define SB_KHI (SB_QLO + 128 * ROWB)
#define SB_KLO (SB_KHI + 64 * ROWB)
#define SB_VHI (SB_KLO + 64 * ROWB)
#define SB_VLO (SB_VHI + 64 * ROWB)
#define ATT_SMEM (SB_VLO + 64 * ROWB)  // 204800

__global__ __launch_bounds__(256) void attn_kernel()
{
    extern __shared__ char smem[];
    const uint32_t sb = smem_to_u32(smem);
    const int tid = threadIdx.x;
    const int wid = tid >> 5;
    const int lane = tid & 31;
    const int bh = blockIdx.y;
    const int row0 = blockIdx.x * 128;

    const size_t qbase = (size_t)bh * NTOK + row0;
    const size_t kvbase = (size_t)bh * NTOK;

    {
#pragma unroll
        for (int i = 0; i < 12; i++) {
            int idx = tid + 256 * i;
            int row = idx / 24, ch = idx - row * 24;
            size_t src = (size_t)(ch >> 3) * SLABQ + (qbase + row) * 64 + (ch & 7) * 8;
            cpasync16(sb + SB_QHI + row * ROWB + ch * 16, g_Qhi + src);
            cpasync16(sb + SB_QLO + row * ROWB + ch * 16, g_Qlo + src);
        }
#pragma unroll
        for (int i = 0; i < 6; i++) {
            int idx = tid + 256 * i;
            int row = idx / 24, ch = idx - row * 24;
            size_t src = (size_t)(ch >> 3) * SLABQ + (kvbase + row) * 64 + (ch & 7) * 8;
            cpasync16(sb + SB_KHI + row * ROWB + ch * 16, g_Khi + src);
            cpasync16(sb + SB_KLO + row * ROWB + ch * 16, g_Klo + src);
            cpasync16(sb + SB_VHI + row * ROWB + ch * 16, g_Vhi + src);
            cpasync16(sb + SB_VLO + row * ROWB + ch * 16, g_Vlo + src);
        }
        CP_COMMIT();
        CP_WAIT0();
    }
    __syncthreads();

    const uint32_t aQrow = (uint32_t)(wid * 16 + (lane & 15));
    const uint32_t aQcol = (uint32_t)((lane >> 4) * 8);
    const uint32_t adrQhi = sb + SB_QHI + aQrow * ROWB + aQcol * 2;
    const uint32_t adrQlo = sb + SB_QLO + aQrow * ROWB + aQcol * 2;
    const uint32_t nK = (uint32_t)((lane & 7) + ((lane >> 4) << 3));
    const uint32_t kK = (uint32_t)((lane & 8));
    const uint32_t adrKhi = sb + SB_KHI + nK * ROWB + kK * 2;
    const uint32_t adrKlo = sb + SB_KLO + nK * ROWB + kK * 2;
    const uint32_t kV = (uint32_t)(lane & 15);
    const uint32_t nV = (uint32_t)((lane >> 4) * 8);
    const uint32_t adrVhi = sb + SB_VHI + kV * ROWB + nV * 2;
    const uint32_t adrVlo = sb + SB_VLO + kV * ROWB + nV * 2;

    float O[24][4];
#pragma unroll
    for (int i = 0; i < 24; i++)
#pragma unroll
        for (int e = 0; e < 4; e++) O[i][e] = 0.0f;
    float lacc0 = 0.0f, lacc1 = 0.0f;

    for (int kt = 0; kt < 32; kt++) {
        // ---- S = Q K^T, pass-grouped (8 independent chains per pass) ----
        float c[8][4];
#pragma unroll
        for (int i = 0; i < 8; i++)
#pragma unroll
            for (int e = 0; e < 4; e++) c[i][e] = 0.0f;

#pragma unroll
        for (int ks = 0; ks < 12; ks++) {
            uint32_t ahi[4], alo[4];
            LDSM4(ahi, adrQhi + ks * 32);
            LDSM4(alo, adrQlo + ks * 32);
            uint32_t bhh[4][4], bll[4][4];
#pragma unroll
            for (int ng = 0; ng < 4; ng++) {
                LDSM4(bhh[ng], adrKhi + ng * (16 * ROWB) + ks * 32);
                LDSM4(bll[ng], adrKlo + ng * (16 * ROWB) + ks * 32);
            }
#pragma unroll
            for (int ng = 0; ng < 4; ng++) {
                MMA16816(c[2 * ng],     ahi, bhh[ng][0], bhh[ng][1]);
                MMA16816(c[2 * ng + 1], ahi, bhh[ng][2], bhh[ng][3]);
            }
#pragma unroll
            for (int ng = 0; ng < 4; ng++) {
                MMA16816(c[2 * ng],     ahi, bll[ng][0], bll[ng][1]);
                MMA16816(c[2 * ng + 1], ahi, bll[ng][2], bll[ng][3]);
            }
#pragma unroll
            for (int ng = 0; ng < 4; ng++) {
                MMA16816(c[2 * ng],     alo, bhh[ng][0], bhh[ng][1]);
                MMA16816(c[2 * ng + 1], alo, bhh[ng][2], bhh[ng][3]);
            }
        }
        __syncthreads();

        // prefetch next K behind softmax + PV
        if (kt + 1 < 32) {
#pragma unroll
            for (int i = 0; i < 6; i++) {
                int idx = tid + 256 * i;
                int row = idx / 24, ch = idx - row * 24;
                size_t src = (size_t)(ch >> 3) * SLABQ
                           + (kvbase + (kt + 1) * 64 + row) * 64 + (ch & 7) * 8;
                cpasync16(sb + SB_KHI + row * ROWB + ch * 16, g_Khi + src);
                cpasync16(sb + SB_KLO + row * ROWB + ch * 16, g_Klo + src);
            }
            CP_COMMIT();
        }

        // ---- softmax (no max-shift) + P -> A-frags ----
        uint32_t pahi[4][4], palo[4][4];
#pragma unroll
        for (int nf = 0; nf < 8; nf++)
#pragma unroll
            for (int e = 0; e < 4; e++) c[nf][e] = __expf(c[nf][e]);
#pragma unroll
        for (int nf = 0; nf < 8; nf++) {
            lacc0 += c[nf][0] + c[nf][1];
            lacc1 += c[nf][2] + c[nf][3];
        }
#pragma unroll
        for (int j = 0; j < 4; j++) {
            splitpk(c[2 * j][0],     c[2 * j][1],     pahi[j][0], palo[j][0]);
            splitpk(c[2 * j][2],     c[2 * j][3],     pahi[j][1], palo[j][1]);
            splitpk(c[2 * j + 1][0], c[2 * j + 1][1], pahi[j][2], palo[j][2]);
            splitpk(c[2 * j + 1][2], c[2 * j + 1][3], pahi[j][3], palo[j][3]);
        }

        // ---- O += P V: ks outer, nc groups of 4, pass-grouped ----
#pragma unroll
        for (int ks = 0; ks < 4; ks++) {
#pragma unroll
            for (int g = 0; g < 3; g++) {
                uint32_t v[4][4], vl[4][4];
#pragma unroll
                for (int j = 0; j < 4; j++) {
                    int nc = g * 4 + j;
                    LDSM4T(v[j],  adrVhi + ks * (16 * ROWB) + nc * 32);
                    LDSM4T(vl[j], adrVlo + ks * (16 * ROWB) + nc * 32);
                }
#pragma unroll
                for (int j = 0; j < 4; j++) {
                    int nc = g * 4 + j;
                    MMA16816(O[2 * nc],     pahi[ks], v[j][0], v[j][1]);
                    MMA16816(O[2 * nc + 1], pahi[ks], v[j][2], v[j][3]);
                }
#pragma unroll
                for (int j = 0; j < 4; j++) {
                    int nc = g * 4 + j;
                    MMA16816(O[2 * nc],     pahi[ks], vl[j][0], vl[j][1]);
                    MMA16816(O[2 * nc + 1], pahi[ks], vl[j][2], vl[j][3]);
                }
#pragma unroll
                for (int j = 0; j < 4; j++) {
                    int nc = g * 4 + j;
                    MMA16816(O[2 * nc],     palo[ks], v[j][0], v[j][1]);
                    MMA16816(O[2 * nc + 1], palo[ks], v[j][2], v[j][3]);
                }
            }
        }
        __syncthreads();

        if (kt + 1 < 32) {
#pragma unroll
            for (int i = 0; i < 6; i++) {
                int idx = tid + 256 * i;
                int row = idx / 24, ch = idx - row * 24;
                size_t src = (size_t)(ch >> 3) * SLABQ
                           + (kvbase + (kt + 1) * 64 + row) * 64 + (ch & 7) * 8;
                cpasync16(sb + SB_VHI + row * ROWB + ch * 16, g_Vhi + src);
                cpasync16(sb + SB_VLO + row * ROWB + ch * 16, g_Vlo + src);
            }
            CP_COMMIT();
            CP_WAIT0();
            __syncthreads();
        }
    }

    lacc0 += __shfl_xor_sync(0xffffffffu, lacc0, 1);
    lacc0 += __shfl_xor_sync(0xffffffffu, lacc0, 2);
    lacc1 += __shfl_xor_sync(0xffffffffu, lacc1, 1);
    lacc1 += __shfl_xor_sync(0xffffffffu, lacc1, 2);
    const float li0 = 1.0f / lacc0;
    const float li1 = 1.0f / lacc1;

    // epilogue: e' = cc*64+dd -> OA[cc][tok][h*64+dd], packed 4B stores
    const int b = bh >> 3, hh = bh & 7;
    const int r0g = row0 + wid * 16 + (lane >> 2);
    const int tok0 = b * NTOK + r0g;
    const int colb = 2 * (lane & 3);
#pragma unroll
    for (int nc = 0; nc < 12; nc++) {
#pragma unroll
        for (int f = 0; f < 2; f++) {
            int col = nc * 16 + f * 8 + colb;     // even
            int ccc = col >> 6, dd = col & 63;
            size_t a0 = ((size_t)(ccc * TOKS) + tok0) * DI + hh * 64 + dd;
            uint32_t h0, l0, h1, l1;
            splitpk(O[2 * nc + f][0] * li0, O[2 * nc + f][1] * li0, h0, l0);
            splitpk(O[2 * nc + f][2] * li1, O[2 * nc + f][3] * li1, h1, l1);
            *(uint32_t*)&g_OAhi[a0] = h0;
            *(uint32_t*)&g_OAlo[a0] = l0;
            *(uint32_t*)&g_OAhi[a0 + 8 * DI] = h1;
            *(uint32_t*)&g_OAlo[a0 + 8 * DI] = l1;
        }
    }
}

// ============================================================================
extern "C" void kernel_launch(void* const* d_in, const int* in_sizes, int n_in,
                              void* d_out, int out_size)
{
    const float* x  = (const float*)d_in[0];
    const float* Wq = (const float*)d_in[1];
    const float* Wk = (const float*)d_in[2];
    const float* Wv = (const float*)d_in[3];
    const float* Wo = (const float*)d_in[4];
    float* out = (float*)d_out;

    cudaFuncSetAttribute(attn_kernel,
        cudaFuncAttributeMaxDynamicSharedMemorySize, ATT_SMEM);
    cudaFuncSetAttribute(qkv_hmma,
        cudaFuncAttributeMaxDynamicSharedMemorySize, GEMM_SMEM);
    cudaFuncSetAttribute(oproj_hmma,
        cudaFuncAttributeMaxDynamicSharedMemorySize, GEMM_SMEM);

    prep_x_kernel<<<X_ELEMS / 256, 256>>>(x);
    prep_w_kernel<<<(4 * W_ONE) / 256, 256>>>(Wq, Wk, Wv, Wo);
    qkv_hmma<<<dim3(32, 4, 9), 256, GEMM_SMEM>>>(0.0f);
    attn_kernel<<<dim3(16, 16), 256, ATT_SMEM>>>();
    oproj_hmma<<<dim3(32, 2, 3), 256, GEMM_SMEM>>>(out);
}